// round 3
// baseline (speedup 1.0000x reference)
#include <cuda_runtime.h>
#include <math.h>

#define BB 16
#define NN 1024
#define IND 256
#define HH 4
#define DD 64
#define HD 256
#define NEGV -1.0e9f
#define EPSV 1e-5f

// Scratch (no allocations allowed)
__device__ float g_h[BB * NN * HD];      // projected features [b,n,H*D]
__device__ float g_src[BB * NN * HH];    // src logits [b,n,H]
__device__ float g_dst[BB * NN * HH];    // dst logits [b,n,H]
__device__ float g_att[BB * NN * HD];    // attention output pre-LN

// ---------------------------------------------------------------------------
// Kernel 1: h = x @ W   (M=16384, N=256, K=256) fp32 tiled SGEMM
// ---------------------------------------------------------------------------
__global__ __launch_bounds__(256) void gemm_k(const float* __restrict__ A,
                                              const float* __restrict__ Wm) {
    __shared__ float As[16][68];
    __shared__ float Bs[16][68];
    int bm = blockIdx.x;          // 256 tiles of 64 rows
    int bn = blockIdx.y;          // 4 tiles of 64 cols
    int tid = threadIdx.x;
    int tx = tid & 15, ty = tid >> 4;
    int arow = tid >> 2, acol = (tid & 3) * 4;
    int brow = tid >> 4, bcol = (tid & 15) * 4;
    const float* Ap = A + (size_t)(bm * 64 + arow) * IND;
    const float* Bp = Wm + (size_t)bn * 64;
    float acc[4][4] = {};
    for (int k0 = 0; k0 < IND; k0 += 16) {
        float4 a4 = *(const float4*)(Ap + k0 + acol);
        As[acol + 0][arow] = a4.x;
        As[acol + 1][arow] = a4.y;
        As[acol + 2][arow] = a4.z;
        As[acol + 3][arow] = a4.w;
        float4 b4 = *(const float4*)(Bp + (size_t)(k0 + brow) * HD + bcol);
        *(float4*)&Bs[brow][bcol] = b4;
        __syncthreads();
#pragma unroll
        for (int kk = 0; kk < 16; kk++) {
            float av[4], bv[4];
#pragma unroll
            for (int i = 0; i < 4; i++) av[i] = As[kk][ty * 4 + i];
#pragma unroll
            for (int j = 0; j < 4; j++) bv[j] = Bs[kk][tx * 4 + j];
#pragma unroll
            for (int i = 0; i < 4; i++)
#pragma unroll
                for (int j = 0; j < 4; j++) acc[i][j] += av[i] * bv[j];
        }
        __syncthreads();
    }
#pragma unroll
    for (int i = 0; i < 4; i++) {
        float* o = g_h + (size_t)(bm * 64 + ty * 4 + i) * HD + bn * 64 + tx * 4;
        *(float4*)o = make_float4(acc[i][0], acc[i][1], acc[i][2], acc[i][3]);
    }
}

// ---------------------------------------------------------------------------
// Kernel 2: src/dst = einsum('nhd,hd->nh')  (one warp per (row, head))
// ---------------------------------------------------------------------------
__global__ __launch_bounds__(128) void srcdst_k(const float* __restrict__ asrc,
                                                const float* __restrict__ adst) {
    int row = blockIdx.x;              // 0 .. B*N-1
    int w = threadIdx.x >> 5;          // head
    int lane = threadIdx.x & 31;
    const float* hr = g_h + (size_t)row * HD + w * DD;
    float h0 = hr[lane], h1 = hr[lane + 32];
    float s1 = h0 * asrc[w * DD + lane] + h1 * asrc[w * DD + lane + 32];
    float s2 = h0 * adst[w * DD + lane] + h1 * adst[w * DD + lane + 32];
#pragma unroll
    for (int o = 16; o > 0; o >>= 1) {
        s1 += __shfl_down_sync(0xffffffffu, s1, o);
        s2 += __shfl_down_sync(0xffffffffu, s2, o);
    }
    if (lane == 0) {
        g_src[row * HH + w] = s1;
        g_dst[row * HH + w] = s2;
    }
}

// ---------------------------------------------------------------------------
// Kernel 3: fused scores + masked softmax (online) + alpha @ V
// One block = (batch b, head hh, 64-row i-tile). Streams 64-wide j-tiles.
// ---------------------------------------------------------------------------
__global__ __launch_bounds__(256) void attn_k(const int* __restrict__ adj,
                                              const int* __restrict__ mask) {
    __shared__ float Vt[64][68];      // V tile [j][d]
    __shared__ float Pt[64][68];      // probs tile [i][j]
    __shared__ float dstS[64];
    __shared__ float srcS[64];
    __shared__ int mJ[64];
    __shared__ int mI[64];
    __shared__ float mS[64], lS[64], scS[64];

    int it = blockIdx.x, hh = blockIdx.y, b = blockIdx.z;
    int i0 = it * 64;
    int tid = threadIdx.x;
    int ti = tid >> 2, q = tid & 3;        // score-phase mapping: 4 threads/row
    int iy = tid >> 4, ix = tid & 15;      // accumulate mapping: 4x4 reg tile

    if (tid < 64) {
        srcS[tid] = g_src[(size_t)(b * NN + i0 + tid) * HH + hh];
        mI[tid] = mask[b * NN + i0 + tid];
        mS[tid] = -INFINITY;
        lS[tid] = 0.f;
        scS[tid] = 0.f;
    }
    float acc[4][4] = {};
    const float* hb = g_h + (size_t)(b * NN) * HD + hh * DD;
    const int* adjb = adj + (size_t)(b * NN + i0) * NN;

    for (int j0 = 0; j0 < NN; j0 += 64) {
        // --- load V tile + dst/mask for this j tile ---
        {
            const float* vr = hb + (size_t)(j0 + ti) * HD + q * 16;
            float4 v0 = ((const float4*)vr)[0];
            float4 v1 = ((const float4*)vr)[1];
            float4 v2 = ((const float4*)vr)[2];
            float4 v3 = ((const float4*)vr)[3];
            float* vd = &Vt[ti][q * 16];
            ((float4*)vd)[0] = v0;
            ((float4*)vd)[1] = v1;
            ((float4*)vd)[2] = v2;
            ((float4*)vd)[3] = v3;
        }
        if (tid < 64) {
            dstS[tid] = g_dst[(size_t)(b * NN + j0 + tid) * HH + hh];
            mJ[tid] = mask[b * NN + j0 + tid];
        }
        __syncthreads();

        // --- score phase: row ti, 16 j's per thread ---
        {
            float si = srcS[ti];
            bool rv = mI[ti] > 0;
            float mold = mS[ti];
            const int4* arow = (const int4*)(adjb + (size_t)ti * NN + j0 + q * 16);
            float e[16];
            float mloc = -INFINITY;
#pragma unroll
            for (int k4 = 0; k4 < 4; k4++) {
                int4 a = arow[k4];
                int av[4] = {a.x, a.y, a.z, a.w};
#pragma unroll
                for (int c = 0; c < 4; c++) {
                    int jj = q * 16 + k4 * 4 + c;
                    float ev = si + dstS[jj];
                    ev = ev > 0.f ? ev : 0.2f * ev;
                    bool v = rv && (av[c] > 0) && (mJ[jj] > 0);
                    ev = v ? ev : NEGV;
                    e[k4 * 4 + c] = ev;
                    mloc = fmaxf(mloc, ev);
                }
            }
            mloc = fmaxf(mloc, __shfl_xor_sync(0xffffffffu, mloc, 1));
            mloc = fmaxf(mloc, __shfl_xor_sync(0xffffffffu, mloc, 2));
            float mnew = fmaxf(mold, mloc);
            float ls = 0.f;
            float* pr = &Pt[ti][q * 16];
#pragma unroll
            for (int k4 = 0; k4 < 4; k4++) {
                float4 p4;
                p4.x = __expf(e[k4 * 4 + 0] - mnew);
                p4.y = __expf(e[k4 * 4 + 1] - mnew);
                p4.z = __expf(e[k4 * 4 + 2] - mnew);
                p4.w = __expf(e[k4 * 4 + 3] - mnew);
                ls += p4.x + p4.y + p4.z + p4.w;
                ((float4*)pr)[k4] = p4;
            }
            ls += __shfl_xor_sync(0xffffffffu, ls, 1);
            ls += __shfl_xor_sync(0xffffffffu, ls, 2);
            if (q == 0) {
                float sc = __expf(mold - mnew);
                scS[ti] = sc;
                lS[ti] = lS[ti] * sc + ls;
                mS[ti] = mnew;
            }
        }
        __syncthreads();

        // --- accumulate: acc[r][c] for rows iy*4+r, dims ix*4+c ---
        {
#pragma unroll
            for (int r = 0; r < 4; r++) {
                float sc = scS[iy * 4 + r];
#pragma unroll
                for (int c = 0; c < 4; c++) acc[r][c] *= sc;
            }
#pragma unroll 8
            for (int kk = 0; kk < 64; kk++) {
                float4 vv = *(const float4*)&Vt[kk][ix * 4];
#pragma unroll
                for (int r = 0; r < 4; r++) {
                    float p = Pt[iy * 4 + r][kk];
                    acc[r][0] += p * vv.x;
                    acc[r][1] += p * vv.y;
                    acc[r][2] += p * vv.z;
                    acc[r][3] += p * vv.w;
                }
            }
        }
        __syncthreads();
    }

    // --- epilogue: normalize by l, write out ---
#pragma unroll
    for (int r = 0; r < 4; r++) {
        int row = i0 + iy * 4 + r;
        float inv = 1.0f / lS[iy * 4 + r];
        float* o = g_att + (size_t)(b * NN + row) * HD + hh * DD + ix * 4;
        *(float4*)o = make_float4(acc[r][0] * inv, acc[r][1] * inv,
                                  acc[r][2] * inv, acc[r][3] * inv);
    }
}

// ---------------------------------------------------------------------------
// Kernel 4: out = LayerNorm(att * mask_i) * gamma + beta
// ---------------------------------------------------------------------------
__global__ __launch_bounds__(256) void ln_k(const int* __restrict__ mask,
                                            const float* __restrict__ gamma,
                                            const float* __restrict__ beta,
                                            float* __restrict__ out) {
    int row = blockIdx.x;  // 0..B*N-1
    int t = threadIdx.x;
    float mf = mask[row] > 0 ? 1.f : 0.f;
    float v = g_att[(size_t)row * HD + t] * mf;
    float s = v, s2 = v * v;
#pragma unroll
    for (int o = 16; o > 0; o >>= 1) {
        s += __shfl_down_sync(0xffffffffu, s, o);
        s2 += __shfl_down_sync(0xffffffffu, s2, o);
    }
    __shared__ float ws[8], ws2[8];
    int w = t >> 5, lane = t & 31;
    if (lane == 0) { ws[w] = s; ws2[w] = s2; }
    __syncthreads();
    if (t == 0) {
        float a = 0.f, bsum = 0.f;
#pragma unroll
        for (int i = 0; i < 8; i++) { a += ws[i]; bsum += ws2[i]; }
        ws[0] = a;
        ws2[0] = bsum;
    }
    __syncthreads();
    float mu = ws[0] * (1.0f / HD);
    float var = ws2[0] * (1.0f / HD) - mu * mu;
    out[(size_t)row * HD + t] = (v - mu) * rsqrtf(var + EPSV) * gamma[t] + beta[t];
}

// ---------------------------------------------------------------------------
extern "C" void kernel_launch(void* const* d_in, const int* in_sizes, int n_in,
                              void* d_out, int out_size) {
    const float* x = (const float*)d_in[0];
    const int* adj = (const int*)d_in[1];
    const int* mask = (const int*)d_in[2];
    const float* Wm = (const float*)d_in[3];
    const float* a_src = (const float*)d_in[4];
    const float* a_dst = (const float*)d_in[5];
    const float* gamma = (const float*)d_in[6];
    const float* beta = (const float*)d_in[7];
    float* out = (float*)d_out;

    dim3 gg(BB * NN / 64, HD / 64);
    gemm_k<<<gg, 256>>>(x, Wm);
    srcdst_k<<<BB * NN, 128>>>(a_src, a_dst);
    dim3 ga(NN / 64, HH, BB);
    attn_k<<<ga, 256>>>(adj, mask);
    ln_k<<<BB * NN, 256>>>(mask, gamma, beta, out);
}